// round 2
// baseline (speedup 1.0000x reference)
#include <cuda_runtime.h>
#include <cstdint>
#include <cstddef>

#define N_NODES 50000
#define N_REL   8
#define CH      128

// Scratch for x_transformed: [R, N, C] fp32 = 204.8 MB (static __device__ array,
// the sanctioned no-cudaMalloc workaround).
__device__ float g_xt[(size_t)N_REL * N_NODES * CH];

// ---------------------------------------------------------------------------
// helpers
// ---------------------------------------------------------------------------
__device__ __forceinline__ uint32_t cvt_tf32(float f) {
    uint32_t r;
    asm("cvt.rna.tf32.f32 %0, %1;" : "=r"(r) : "f"(f));
    return r;
}

__device__ __forceinline__ void mma_tf32(float* d, const uint32_t* a, const uint32_t* b) {
    asm volatile(
        "mma.sync.aligned.m16n8k8.row.col.f32.tf32.tf32.f32 "
        "{%0,%1,%2,%3}, {%4,%5,%6,%7}, {%8,%9}, {%0,%1,%2,%3};\n"
        : "+f"(d[0]), "+f"(d[1]), "+f"(d[2]), "+f"(d[3])
        : "r"(a[0]), "r"(a[1]), "r"(a[2]), "r"(a[3]),
          "r"(b[0]), "r"(b[1]));
}

// ---------------------------------------------------------------------------
// Kernel 1: out[n][c] = bias[c]   (out is poisoned; init + bias fold)
// ---------------------------------------------------------------------------
__global__ __launch_bounds__(256) void init_out_kernel(float* __restrict__ out,
                                                       const float* __restrict__ bias,
                                                       int total) {
    int i = blockIdx.x * 256 + threadIdx.x;
    if (i < total) out[i] = bias[i & (CH - 1)];
}

// ---------------------------------------------------------------------------
// Kernel 2: g_xt[r][n][:] = x[n][:] @ W[r]   (tf32 mma.sync GEMM)
// Block: 256 threads (8 warps), computes 128 rows x 128 cols for one relation.
// K processed in chunks of 32 through shared memory.
// Warp grid: 2 (m) x 4 (n); each warp: 64 rows x 32 cols = 4x4 m16n8 tiles.
// ---------------------------------------------------------------------------
__global__ __launch_bounds__(256) void transform_kernel(const float* __restrict__ x,
                                                        const float* __restrict__ w) {
    __shared__ float As[128][36];   // 128 rows x 32 k (+pad 4): conflict-free frag reads
    __shared__ float Bs[32][136];   // 32 k x 128 cols (+pad 8): conflict-free frag reads

    const int row0 = blockIdx.x * 128;
    const int rel  = blockIdx.y;
    const float* W = w + (size_t)rel * CH * CH;

    const int tid  = threadIdx.x;
    const int warp = tid >> 5;
    const int lane = tid & 31;
    const int g    = lane >> 2;      // groupID (0..7)
    const int tig  = lane & 3;       // thread-in-group (0..3)
    const int wm   = warp & 1;       // 0..1  -> 64-row half
    const int wn   = warp >> 1;      // 0..3  -> 32-col quarter

    float acc[4][4][4];
    #pragma unroll
    for (int mi = 0; mi < 4; mi++)
        #pragma unroll
        for (int ni = 0; ni < 4; ni++)
            #pragma unroll
            for (int q = 0; q < 4; q++) acc[mi][ni][q] = 0.f;

    for (int kc = 0; kc < CH; kc += 32) {
        // ---- load A tile: 128 rows x 32 k  (1024 float4, 4 per thread) ----
        #pragma unroll
        for (int it = 0; it < 4; it++) {
            int idx = it * 256 + tid;          // 0..1023
            int row = idx >> 3;                // 8 float4 per row
            int c4  = idx & 7;
            float4 v = make_float4(0.f, 0.f, 0.f, 0.f);
            int grow = row0 + row;
            if (grow < N_NODES)
                v = *(const float4*)(x + (size_t)grow * CH + kc + c4 * 4);
            *(float4*)(&As[row][c4 * 4]) = v;
        }
        // ---- load B tile: 32 k x 128 cols (1024 float4, 4 per thread) ----
        #pragma unroll
        for (int it = 0; it < 4; it++) {
            int idx  = it * 256 + tid;         // 0..1023
            int rowk = idx >> 5;               // 32 float4 per row
            int c4   = idx & 31;
            float4 v = *(const float4*)(W + (size_t)(kc + rowk) * CH + c4 * 4);
            *(float4*)(&Bs[rowk][c4 * 4]) = v;
        }
        __syncthreads();

        #pragma unroll
        for (int k0 = 0; k0 < 32; k0 += 8) {
            uint32_t a[4][4];
            #pragma unroll
            for (int mi = 0; mi < 4; mi++) {
                int rb = wm * 64 + mi * 16 + g;
                a[mi][0] = cvt_tf32(As[rb][k0 + tig]);
                a[mi][1] = cvt_tf32(As[rb + 8][k0 + tig]);
                a[mi][2] = cvt_tf32(As[rb][k0 + tig + 4]);
                a[mi][3] = cvt_tf32(As[rb + 8][k0 + tig + 4]);
            }
            uint32_t b[4][2];
            #pragma unroll
            for (int ni = 0; ni < 4; ni++) {
                int cb = wn * 32 + ni * 8 + g;
                b[ni][0] = cvt_tf32(Bs[k0 + tig][cb]);
                b[ni][1] = cvt_tf32(Bs[k0 + tig + 4][cb]);
            }
            #pragma unroll
            for (int mi = 0; mi < 4; mi++)
                #pragma unroll
                for (int ni = 0; ni < 4; ni++)
                    mma_tf32(acc[mi][ni], a[mi], b[ni]);
        }
        __syncthreads();
    }

    // ---- store C tile to g_xt ----
    float* outb = g_xt + (size_t)rel * N_NODES * CH;
    #pragma unroll
    for (int mi = 0; mi < 4; mi++) {
        int r1 = row0 + wm * 64 + mi * 16 + g;
        int r2 = r1 + 8;
        #pragma unroll
        for (int ni = 0; ni < 4; ni++) {
            int c = wn * 32 + ni * 8 + tig * 2;
            if (r1 < N_NODES) {
                float2 v = make_float2(acc[mi][ni][0], acc[mi][ni][1]);
                *(float2*)(outb + (size_t)r1 * CH + c) = v;
            }
            if (r2 < N_NODES) {
                float2 v = make_float2(acc[mi][ni][2], acc[mi][ni][3]);
                *(float2*)(outb + (size_t)r2 * CH + c) = v;
            }
        }
    }
}

// ---------------------------------------------------------------------------
// Kernel 3: per-edge gather + atomic scatter-add.
// 1 warp per edge: lanes read 32 x float4 (512B) of x_t[type, col], RED into
// out[row] (L2-resident, 25.6 MB).
// NOTE: edge_index / edge_type are INT32 (JAX default disables x64; the
// reference's jnp.int64 request silently degrades to int32).
// ---------------------------------------------------------------------------
__global__ __launch_bounds__(256) void edge_kernel(const int* __restrict__ ei,
                                                   const int* __restrict__ et,
                                                   float* __restrict__ out,
                                                   int E) {
    int e = (blockIdx.x * 256 + threadIdx.x) >> 5;
    if (e >= E) return;
    int lane = threadIdx.x & 31;

    int row = ei[e];
    int col = ei[E + e];
    int t   = et[e];

    // Defensive guards: if the dtype assumption is wrong, fail with a
    // rel_err diagnostic instead of an illegal access.
    if ((unsigned)row >= N_NODES || (unsigned)col >= N_NODES || (unsigned)t >= N_REL)
        return;

    const float4* src = (const float4*)(g_xt + ((size_t)t * N_NODES + (size_t)col) * CH);
    float4 v = src[lane];

    float* o = out + (size_t)row * CH + lane * 4;
    atomicAdd(o + 0, v.x);
    atomicAdd(o + 1, v.y);
    atomicAdd(o + 2, v.z);
    atomicAdd(o + 3, v.w);
}

// ---------------------------------------------------------------------------
// kernel_launch
// inputs (metadata order): x f32[50000*128], edge_index i32[2*640000],
//                          edge_type i32[640000], weight f32[8*128*128],
//                          bias f32[128]
// ---------------------------------------------------------------------------
extern "C" void kernel_launch(void* const* d_in, const int* in_sizes, int n_in,
                              void* d_out, int out_size) {
    const float* x    = (const float*)d_in[0];
    const int*   ei   = (const int*)d_in[1];
    const int*   et   = (const int*)d_in[2];
    const float* w    = (const float*)d_in[3];
    const float* bias = (const float*)d_in[4];
    float* out = (float*)d_out;

    const int E = in_sizes[2];

    // 1) out = bias (also clears the 0xAA poison)
    init_out_kernel<<<(N_NODES * CH + 255) / 256, 256>>>(out, bias, N_NODES * CH);

    // 2) x_t[r] = x @ W[r]  (tf32 tensor-core GEMM)
    dim3 grid((N_NODES + 127) / 128, N_REL);
    transform_kernel<<<grid, 256>>>(x, w);

    // 3) gather + scatter-add per edge
    int eblocks = (E + 7) / 8;   // 8 edges (warps) per 256-thread block
    edge_kernel<<<eblocks, 256>>>(ei, et, out, E);
}

// round 3
// speedup vs baseline: 1.2425x; 1.2425x over previous
#include <cuda_runtime.h>
#include <cstdint>
#include <cstddef>

#define N_NODES 50000
#define N_EDGES 640000
#define N_REL   8
#define CH      128

// Scratch (static __device__ arrays — the sanctioned no-cudaMalloc route)
__device__ float g_xt[(size_t)N_REL * N_NODES * CH];   // 204.8 MB: x @ W[r]
__device__ int   g_hist[N_NODES];                      // per-dest-row edge count
__device__ int   g_start[N_NODES + 1];                 // exclusive prefix (segments)
__device__ int   g_cursor[N_NODES];                    // scatter cursors
__device__ int   g_sorted[N_EDGES];                    // fused key: t*N_NODES+col

// ---------------------------------------------------------------------------
// helpers
// ---------------------------------------------------------------------------
__device__ __forceinline__ uint32_t cvt_tf32(float f) {
    uint32_t r;
    asm("cvt.rna.tf32.f32 %0, %1;" : "=r"(r) : "f"(f));
    return r;
}

__device__ __forceinline__ void mma_tf32(float* d, const uint32_t* a, const uint32_t* b) {
    asm volatile(
        "mma.sync.aligned.m16n8k8.row.col.f32.tf32.tf32.f32 "
        "{%0,%1,%2,%3}, {%4,%5,%6,%7}, {%8,%9}, {%0,%1,%2,%3};\n"
        : "+f"(d[0]), "+f"(d[1]), "+f"(d[2]), "+f"(d[3])
        : "r"(a[0]), "r"(a[1]), "r"(a[2]), "r"(a[3]),
          "r"(b[0]), "r"(b[1]));
}

// ---------------------------------------------------------------------------
// Sort phase 0: zero the histogram (graph replays need fresh state)
// ---------------------------------------------------------------------------
__global__ __launch_bounds__(256) void zero_hist_kernel() {
    int i = blockIdx.x * 256 + threadIdx.x;
    if (i < N_NODES) g_hist[i] = 0;
}

// ---------------------------------------------------------------------------
// Sort phase 1: histogram of destination rows
// ---------------------------------------------------------------------------
__global__ __launch_bounds__(256) void hist_kernel(const int* __restrict__ ei, int E) {
    int e = blockIdx.x * 256 + threadIdx.x;
    if (e >= E) return;
    int row = ei[e];
    if ((unsigned)row < N_NODES) atomicAdd(&g_hist[row], 1);
}

// ---------------------------------------------------------------------------
// Sort phase 2: exclusive prefix scan over 50000 bins (single block, chunked)
// Also initializes g_cursor = g_start.
// ---------------------------------------------------------------------------
__global__ __launch_bounds__(1024) void scan_kernel() {
    __shared__ int s[1024];
    const int tid = threadIdx.x;
    int carry = 0;
    for (int base = 0; base < N_NODES; base += 1024) {
        int i = base + tid;
        int v = (i < N_NODES) ? g_hist[i] : 0;
        s[tid] = v;
        __syncthreads();
        #pragma unroll
        for (int off = 1; off < 1024; off <<= 1) {
            int t = (tid >= off) ? s[tid - off] : 0;
            __syncthreads();
            s[tid] += t;
            __syncthreads();
        }
        int incl = s[tid];
        int excl = incl - v;
        if (i < N_NODES) {
            g_start[i]  = carry + excl;
            g_cursor[i] = carry + excl;
        }
        int chunk_total = s[1023];
        __syncthreads();
        carry += chunk_total;
    }
    if (tid == 0) g_start[N_NODES] = carry;
}

// ---------------------------------------------------------------------------
// Sort phase 3: scatter fused gather-keys into destination segments
// ---------------------------------------------------------------------------
__global__ __launch_bounds__(256) void scatter_kernel(const int* __restrict__ ei,
                                                      const int* __restrict__ et,
                                                      int E) {
    int e = blockIdx.x * 256 + threadIdx.x;
    if (e >= E) return;
    int row = ei[e];
    int col = ei[E + e];
    int t   = et[e];
    if ((unsigned)row >= N_NODES || (unsigned)col >= N_NODES || (unsigned)t >= N_REL)
        return;
    int pos = atomicAdd(&g_cursor[row], 1);
    g_sorted[pos] = t * N_NODES + col;
}

// ---------------------------------------------------------------------------
// Transform: g_xt[r][n][:] = x[n][:] @ W[r]   (tf32 mma.sync GEMM)
// ---------------------------------------------------------------------------
__global__ __launch_bounds__(256) void transform_kernel(const float* __restrict__ x,
                                                        const float* __restrict__ w) {
    __shared__ float As[128][36];
    __shared__ float Bs[32][136];

    const int row0 = blockIdx.x * 128;
    const int rel  = blockIdx.y;
    const float* W = w + (size_t)rel * CH * CH;

    const int tid  = threadIdx.x;
    const int warp = tid >> 5;
    const int lane = tid & 31;
    const int g    = lane >> 2;
    const int tig  = lane & 3;
    const int wm   = warp & 1;
    const int wn   = warp >> 1;

    float acc[4][4][4];
    #pragma unroll
    for (int mi = 0; mi < 4; mi++)
        #pragma unroll
        for (int ni = 0; ni < 4; ni++)
            #pragma unroll
            for (int q = 0; q < 4; q++) acc[mi][ni][q] = 0.f;

    for (int kc = 0; kc < CH; kc += 32) {
        #pragma unroll
        for (int it = 0; it < 4; it++) {
            int idx = it * 256 + tid;
            int row = idx >> 3;
            int c4  = idx & 7;
            float4 v = make_float4(0.f, 0.f, 0.f, 0.f);
            int grow = row0 + row;
            if (grow < N_NODES)
                v = *(const float4*)(x + (size_t)grow * CH + kc + c4 * 4);
            *(float4*)(&As[row][c4 * 4]) = v;
        }
        #pragma unroll
        for (int it = 0; it < 4; it++) {
            int idx  = it * 256 + tid;
            int rowk = idx >> 5;
            int c4   = idx & 31;
            float4 v = *(const float4*)(W + (size_t)(kc + rowk) * CH + c4 * 4);
            *(float4*)(&Bs[rowk][c4 * 4]) = v;
        }
        __syncthreads();

        #pragma unroll
        for (int k0 = 0; k0 < 32; k0 += 8) {
            uint32_t a[4][4];
            #pragma unroll
            for (int mi = 0; mi < 4; mi++) {
                int rb = wm * 64 + mi * 16 + g;
                a[mi][0] = cvt_tf32(As[rb][k0 + tig]);
                a[mi][1] = cvt_tf32(As[rb + 8][k0 + tig]);
                a[mi][2] = cvt_tf32(As[rb][k0 + tig + 4]);
                a[mi][3] = cvt_tf32(As[rb + 8][k0 + tig + 4]);
            }
            uint32_t b[4][2];
            #pragma unroll
            for (int ni = 0; ni < 4; ni++) {
                int cb = wn * 32 + ni * 8 + g;
                b[ni][0] = cvt_tf32(Bs[k0 + tig][cb]);
                b[ni][1] = cvt_tf32(Bs[k0 + tig + 4][cb]);
            }
            #pragma unroll
            for (int mi = 0; mi < 4; mi++)
                #pragma unroll
                for (int ni = 0; ni < 4; ni++)
                    mma_tf32(acc[mi][ni], a[mi], b[ni]);
        }
        __syncthreads();
    }

    float* outb = g_xt + (size_t)rel * N_NODES * CH;
    #pragma unroll
    for (int mi = 0; mi < 4; mi++) {
        int r1 = row0 + wm * 64 + mi * 16 + g;
        int r2 = r1 + 8;
        #pragma unroll
        for (int ni = 0; ni < 4; ni++) {
            int c = wn * 32 + ni * 8 + tig * 2;
            if (r1 < N_NODES) {
                float2 v = make_float2(acc[mi][ni][0], acc[mi][ni][1]);
                *(float2*)(outb + (size_t)r1 * CH + c) = v;
            }
            if (r2 < N_NODES) {
                float2 v = make_float2(acc[mi][ni][2], acc[mi][ni][3]);
                *(float2*)(outb + (size_t)r2 * CH + c) = v;
            }
        }
    }
}

// ---------------------------------------------------------------------------
// Aggregate: one warp per destination node. Segment-reduce gathered g_xt rows
// (dual accumulators for MLP=2), write out[row] = sum + bias. NO atomics,
// and no separate init kernel (every row written exactly once).
// ---------------------------------------------------------------------------
__global__ __launch_bounds__(256) void aggregate_kernel(const float* __restrict__ bias,
                                                        float* __restrict__ out) {
    int row  = (blockIdx.x * 256 + threadIdx.x) >> 5;
    int lane = threadIdx.x & 31;
    if (row >= N_NODES) return;

    int s = g_start[row];
    int e = g_start[row + 1];

    float4 a0 = make_float4(0.f, 0.f, 0.f, 0.f);
    float4 a1 = make_float4(0.f, 0.f, 0.f, 0.f);

    int i = s;
    for (; i + 1 < e; i += 2) {
        int k0 = g_sorted[i];
        int k1 = g_sorted[i + 1];
        const float4* p0 = (const float4*)(g_xt + (size_t)k0 * CH);
        const float4* p1 = (const float4*)(g_xt + (size_t)k1 * CH);
        float4 v0 = p0[lane];
        float4 v1 = p1[lane];
        a0.x += v0.x; a0.y += v0.y; a0.z += v0.z; a0.w += v0.w;
        a1.x += v1.x; a1.y += v1.y; a1.z += v1.z; a1.w += v1.w;
    }
    if (i < e) {
        int k0 = g_sorted[i];
        const float4* p0 = (const float4*)(g_xt + (size_t)k0 * CH);
        float4 v0 = p0[lane];
        a0.x += v0.x; a0.y += v0.y; a0.z += v0.z; a0.w += v0.w;
    }

    float4 b = ((const float4*)bias)[lane];
    float4 r;
    r.x = a0.x + a1.x + b.x;
    r.y = a0.y + a1.y + b.y;
    r.z = a0.z + a1.z + b.z;
    r.w = a0.w + a1.w + b.w;
    ((float4*)(out + (size_t)row * CH))[lane] = r;
}

// ---------------------------------------------------------------------------
// kernel_launch
// inputs: x f32[50000*128], edge_index i32[2*640000], edge_type i32[640000],
//         weight f32[8*128*128], bias f32[128]
// ---------------------------------------------------------------------------
extern "C" void kernel_launch(void* const* d_in, const int* in_sizes, int n_in,
                              void* d_out, int out_size) {
    const float* x    = (const float*)d_in[0];
    const int*   ei   = (const int*)d_in[1];
    const int*   et   = (const int*)d_in[2];
    const float* w    = (const float*)d_in[3];
    const float* bias = (const float*)d_in[4];
    float* out = (float*)d_out;

    int E = in_sizes[2];
    if (E > N_EDGES) E = N_EDGES;

    // Sort edges by destination row (counting sort)
    zero_hist_kernel<<<(N_NODES + 255) / 256, 256>>>();
    hist_kernel<<<(E + 255) / 256, 256>>>(ei, E);
    scan_kernel<<<1, 1024>>>();
    scatter_kernel<<<(E + 255) / 256, 256>>>(ei, et, E);

    // x_t[r] = x @ W[r]  (tf32 tensor-core GEMM)
    dim3 grid((N_NODES + 127) / 128, N_REL);
    transform_kernel<<<grid, 256>>>(x, w);

    // Segment-reduce per destination node (no atomics), fold bias
    aggregate_kernel<<<(N_NODES * 32 + 255) / 256, 256>>>(bias, out);
}

// round 4
// speedup vs baseline: 1.4814x; 1.1923x over previous
#include <cuda_runtime.h>
#include <cstdint>
#include <cstddef>

#define N_NODES 50000
#define N_EDGES 640000
#define N_REL   8
#define CH      128
#define NBINS   (N_NODES * N_REL)          // 400000 (dest-node, relation) bins
#define SCAN_BLOCKS ((NBINS + 1023) / 1024) // 391

// Scratch (static __device__ arrays — sanctioned no-cudaMalloc route)
__device__ int g_hist[NBINS];
__device__ int g_start[NBINS + 1];
__device__ int g_cursor[NBINS];
__device__ int g_part[SCAN_BLOCKS];
__device__ int g_partoff[SCAN_BLOCKS];
__device__ int g_sorted[N_EDGES];          // source col per sorted edge

// ---------------------------------------------------------------------------
// helpers
// ---------------------------------------------------------------------------
__device__ __forceinline__ uint32_t cvt_tf32(float f) {
    uint32_t r;
    asm("cvt.rna.tf32.f32 %0, %1;" : "=r"(r) : "f"(f));
    return r;
}

__device__ __forceinline__ void mma_tf32(float* d, const uint32_t* a, const uint32_t* b) {
    asm volatile(
        "mma.sync.aligned.m16n8k8.row.col.f32.tf32.tf32.f32 "
        "{%0,%1,%2,%3}, {%4,%5,%6,%7}, {%8,%9}, {%0,%1,%2,%3};\n"
        : "+f"(d[0]), "+f"(d[1]), "+f"(d[2]), "+f"(d[3])
        : "r"(a[0]), "r"(a[1]), "r"(a[2]), "r"(a[3]),
          "r"(b[0]), "r"(b[1]));
}

// ---------------------------------------------------------------------------
// Counting sort by key = row * N_REL + rel
// ---------------------------------------------------------------------------
__global__ __launch_bounds__(256) void zero_hist_kernel() {
    int i = blockIdx.x * 256 + threadIdx.x;
    if (i < NBINS) g_hist[i] = 0;
}

__global__ __launch_bounds__(256) void hist_kernel(const int* __restrict__ ei,
                                                   const int* __restrict__ et, int E) {
    int e = blockIdx.x * 256 + threadIdx.x;
    if (e >= E) return;
    int row = ei[e];
    int t   = et[e];
    if ((unsigned)row < N_NODES && (unsigned)t < N_REL)
        atomicAdd(&g_hist[row * N_REL + t], 1);
}

// scan phase 1: per-block (1024-elem) exclusive scan; block totals to g_part
__global__ __launch_bounds__(1024) void scan1_kernel() {
    __shared__ int s[1024];
    int i = blockIdx.x * 1024 + threadIdx.x;
    int v = (i < NBINS) ? g_hist[i] : 0;
    s[threadIdx.x] = v;
    __syncthreads();
    #pragma unroll
    for (int off = 1; off < 1024; off <<= 1) {
        int t = (threadIdx.x >= off) ? s[threadIdx.x - off] : 0;
        __syncthreads();
        s[threadIdx.x] += t;
        __syncthreads();
    }
    if (i < NBINS) g_start[i] = s[threadIdx.x] - v;   // local exclusive
    if (threadIdx.x == 1023) g_part[blockIdx.x] = s[1023];
}

// scan phase 2: scan the 391 block totals (single block)
__global__ __launch_bounds__(512) void scan2_kernel() {
    __shared__ int s[512];
    int tid = threadIdx.x;
    int v = (tid < SCAN_BLOCKS) ? g_part[tid] : 0;
    s[tid] = v;
    __syncthreads();
    #pragma unroll
    for (int off = 1; off < 512; off <<= 1) {
        int t = (tid >= off) ? s[tid - off] : 0;
        __syncthreads();
        s[tid] += t;
        __syncthreads();
    }
    if (tid < SCAN_BLOCKS) g_partoff[tid] = s[tid] - v;
    if (tid == 511) g_start[NBINS] = s[511];
}

// scan phase 3: add block offsets, init cursors
__global__ __launch_bounds__(256) void scan3_kernel() {
    int i = blockIdx.x * 256 + threadIdx.x;
    if (i >= NBINS) return;
    int v = g_start[i] + g_partoff[i >> 10];
    g_start[i]  = v;
    g_cursor[i] = v;
}

__global__ __launch_bounds__(256) void scatter_kernel(const int* __restrict__ ei,
                                                      const int* __restrict__ et,
                                                      int E) {
    int e = blockIdx.x * 256 + threadIdx.x;
    if (e >= E) return;
    int row = ei[e];
    int col = ei[E + e];
    int t   = et[e];
    if ((unsigned)row >= N_NODES || (unsigned)col >= N_NODES || (unsigned)t >= N_REL)
        return;
    int pos = atomicAdd(&g_cursor[row * N_REL + t], 1);
    g_sorted[pos] = col;
}

// ---------------------------------------------------------------------------
// Fused aggregate + GEMM:
//   out[n,:] = bias + sum_r ( sum_{e in seg(n,r)} x[col_e,:] ) @ W[r]
// Block: 256 threads, 64 dest rows x 128 out cols. Loop r = 0..7:
//   gather-sum x rows (L2-resident, 25.6 MB) into smem As[64][128],
//   then tf32 MMA vs W[r] (K=128 in chunks of 16), accumulating across r.
// No 204.8 MB intermediate; DRAM traffic ~ x + out + edges only.
// ---------------------------------------------------------------------------
__global__ __launch_bounds__(256) void fused_kernel(const float* __restrict__ x,
                                                    const float* __restrict__ w,
                                                    const float* __restrict__ bias,
                                                    float* __restrict__ out) {
    __shared__ float As[64][132];   // pad 4: conflict-free frag reads
    __shared__ float Bs[16][136];   // pad 8

    const int row0 = blockIdx.x * 64;
    const int tid  = threadIdx.x;
    const int warp = tid >> 5;
    const int lane = tid & 31;
    const int g    = lane >> 2;      // 0..7
    const int tig  = lane & 3;       // 0..3
    const int wm   = warp & 1;       // 2 row-halves of 32
    const int wn   = warp >> 1;      // 4 col-quarters of 32

    const float4* x4 = (const float4*)x;

    float acc[2][4][4];
    #pragma unroll
    for (int mi = 0; mi < 2; mi++)
        #pragma unroll
        for (int ni = 0; ni < 4; ni++)
            #pragma unroll
            for (int q = 0; q < 4; q++) acc[mi][ni][q] = 0.f;

    for (int r = 0; r < N_REL; r++) {
        // ---- build As: warp w handles rows w*8 .. w*8+7 ----
        #pragma unroll 1
        for (int sub = 0; sub < 8; sub++) {
            int lrow = warp * 8 + sub;
            int grow = row0 + lrow;
            float4 a = make_float4(0.f, 0.f, 0.f, 0.f);
            if (grow < N_NODES) {
                int bin = grow * N_REL + r;
                int s = g_start[bin];
                int e = g_start[bin + 1];
                for (int i = s; i < e; i++) {
                    int col = g_sorted[i];
                    float4 v = x4[(size_t)col * 32 + lane];
                    a.x += v.x; a.y += v.y; a.z += v.z; a.w += v.w;
                }
            }
            *(float4*)(&As[lrow][lane * 4]) = a;
        }
        __syncthreads();

        const float* W = w + (size_t)r * CH * CH;

        #pragma unroll 1
        for (int kc = 0; kc < CH; kc += 16) {
            // load Bs: 16 k x 128 cols = 512 float4, 2 per thread
            #pragma unroll
            for (int it = 0; it < 2; it++) {
                int idx  = it * 256 + tid;     // 0..511
                int rowk = idx >> 5;           // 32 float4 per row
                int c4   = idx & 31;
                float4 v = *(const float4*)(W + (size_t)(kc + rowk) * CH + c4 * 4);
                *(float4*)(&Bs[rowk][c4 * 4]) = v;
            }
            __syncthreads();

            #pragma unroll
            for (int k0 = 0; k0 < 16; k0 += 8) {
                uint32_t a[2][4];
                #pragma unroll
                for (int mi = 0; mi < 2; mi++) {
                    int rb = wm * 32 + mi * 16 + g;
                    int kk = kc + k0;
                    a[mi][0] = cvt_tf32(As[rb][kk + tig]);
                    a[mi][1] = cvt_tf32(As[rb + 8][kk + tig]);
                    a[mi][2] = cvt_tf32(As[rb][kk + tig + 4]);
                    a[mi][3] = cvt_tf32(As[rb + 8][kk + tig + 4]);
                }
                uint32_t b[4][2];
                #pragma unroll
                for (int ni = 0; ni < 4; ni++) {
                    int cb = wn * 32 + ni * 8 + g;
                    b[ni][0] = cvt_tf32(Bs[k0 + tig][cb]);
                    b[ni][1] = cvt_tf32(Bs[k0 + tig + 4][cb]);
                }
                #pragma unroll
                for (int mi = 0; mi < 2; mi++)
                    #pragma unroll
                    for (int ni = 0; ni < 4; ni++)
                        mma_tf32(acc[mi][ni], a[mi], b[ni]);
            }
            __syncthreads();
        }
        __syncthreads();   // As consumed; safe to rebuild next relation
    }

    // ---- epilogue: out = acc + bias ----
    #pragma unroll
    for (int mi = 0; mi < 2; mi++) {
        int r1 = row0 + wm * 32 + mi * 16 + g;
        int r2 = r1 + 8;
        #pragma unroll
        for (int ni = 0; ni < 4; ni++) {
            int c = wn * 32 + ni * 8 + tig * 2;
            float b0 = bias[c], b1 = bias[c + 1];
            if (r1 < N_NODES) {
                float2 v = make_float2(acc[mi][ni][0] + b0, acc[mi][ni][1] + b1);
                *(float2*)(out + (size_t)r1 * CH + c) = v;
            }
            if (r2 < N_NODES) {
                float2 v = make_float2(acc[mi][ni][2] + b0, acc[mi][ni][3] + b1);
                *(float2*)(out + (size_t)r2 * CH + c) = v;
            }
        }
    }
}

// ---------------------------------------------------------------------------
// kernel_launch
// inputs: x f32[50000*128], edge_index i32[2*640000], edge_type i32[640000],
//         weight f32[8*128*128], bias f32[128]
// ---------------------------------------------------------------------------
extern "C" void kernel_launch(void* const* d_in, const int* in_sizes, int n_in,
                              void* d_out, int out_size) {
    const float* x    = (const float*)d_in[0];
    const int*   ei   = (const int*)d_in[1];
    const int*   et   = (const int*)d_in[2];
    const float* w    = (const float*)d_in[3];
    const float* bias = (const float*)d_in[4];
    float* out = (float*)d_out;

    int E = in_sizes[2];
    if (E > N_EDGES) E = N_EDGES;

    // counting sort by (dest row, relation)
    zero_hist_kernel<<<(NBINS + 255) / 256, 256>>>();
    hist_kernel<<<(E + 255) / 256, 256>>>(ei, et, E);
    scan1_kernel<<<SCAN_BLOCKS, 1024>>>();
    scan2_kernel<<<1, 512>>>();
    scan3_kernel<<<(NBINS + 255) / 256, 256>>>();
    scatter_kernel<<<(E + 255) / 256, 256>>>(ei, et, E);

    // fused aggregate + GEMM + bias
    fused_kernel<<<(N_NODES + 63) / 64, 256>>>(x, w, bias, out);
}